// round 3
// baseline (speedup 1.0000x reference)
#include <cuda_runtime.h>
#include <stdint.h>

#define TT 64          // num types
#define CC 128         // channels
#define TC (TT * CC)   // 8192 stat entries

// ---- device scratch (no allocations allowed) ----
__device__ float2 g_acc[TC];   // {sum, sumsq}
__device__ float  g_cnt[TT];
__device__ float  g_mean[TC];
__device__ float  g_rstd[TC];
__device__ int    g_is64;

// ---------------------------------------------------------------------------
// Kernel 0: zero accumulators + detect int64-vs-int32 type_vec encoding.
// If type_vec is int64 (values 0..63), the int32 view has every odd word == 0.
// ---------------------------------------------------------------------------
__global__ void k_init(const void* __restrict__ tv, long long n) {
    long long idx = (long long)blockIdx.x * blockDim.x + threadIdx.x;
    if (idx < TC) g_acc[idx] = make_float2(0.f, 0.f);
    if (idx < TT) g_cnt[idx] = 0.f;
    if (idx == 0) {
        const int* p = (const int*)tv;
        // Safe to read 256 int32 words: buffer is >= n*4 bytes and n >= 256.
        int lim = (n >= 256) ? 256 : (int)n;
        int is64 = 1;
        for (int i = 1; i < lim; i += 2) {
            if (p[i] != 0) { is64 = 0; break; }
        }
        g_is64 = is64;
    }
}

// ---------------------------------------------------------------------------
// Kernel 1: per-block shared accumulation (exclusive channel ownership),
// then one global-atomic flush per block.
//   blockDim = 128; thread t owns channel t.
//   dyn smem: float2 sacc[TC] (64KB) + float scnt[TT] (256B)
// ---------------------------------------------------------------------------
#define ACC_U 16
__global__ void __launch_bounds__(128) k_acc(
    const float* __restrict__ x, const void* __restrict__ tv, long long N)
{
    extern __shared__ float sm[];
    float2* sacc = (float2*)sm;        // TC entries
    float*  scnt = sm + 2 * TC;        // TT entries
    const int tid = threadIdx.x;

    #pragma unroll
    for (int i = tid; i < TC; i += 128) sacc[i] = make_float2(0.f, 0.f);
    if (tid < TT) scnt[tid] = 0.f;
    __syncthreads();

    const int is64 = g_is64;
    const long long* __restrict__ tv64 = (const long long*)tv;
    const int*       __restrict__ tv32 = (const int*)tv;

    const long long stride = (long long)gridDim.x * ACC_U;
    for (long long r0 = (long long)blockIdx.x * ACC_U; r0 < N; r0 += stride) {
        float xv[ACC_U];
        int   ty[ACC_U];
        const int m = (N - r0 >= ACC_U) ? ACC_U : (int)(N - r0);

        // Batch all loads first -> deep MLP.
        #pragma unroll
        for (int u = 0; u < ACC_U; u++) {
            if (u < m) {
                long long r = r0 + u;
                ty[u] = is64 ? (int)tv64[r] : tv32[r];
                xv[u] = x[r * CC + tid];
            }
        }
        // Exclusive RMW into shared (thread owns its channel column).
        #pragma unroll
        for (int u = 0; u < ACC_U; u++) {
            if (u < m) {
                int o = ty[u] * CC + tid;
                float2 a = sacc[o];
                a.x += xv[u];
                a.y += xv[u] * xv[u];
                sacc[o] = a;
                if (tid == 0) scnt[ty[u]] += 1.f;
            }
        }
    }
    __syncthreads();

    // Flush block partials.
    #pragma unroll
    for (int i = tid; i < TC; i += 128) {
        float2 a = sacc[i];
        atomicAdd(&g_acc[i].x, a.x);
        atomicAdd(&g_acc[i].y, a.y);
    }
    if (tid < TT) {
        float c = scnt[tid];
        if (c != 0.f) atomicAdd(&g_cnt[tid], c);
    }
}

// ---------------------------------------------------------------------------
// Kernel 2: finalize mean / rstd.  (matches reference: var clamped >= 0,
// cnt clamped >= 1, std = sqrt(var + 1e-5))
// ---------------------------------------------------------------------------
__global__ void k_fin() {
    int idx = blockIdx.x * blockDim.x + threadIdx.x;
    if (idx >= TC) return;
    int t = idx / CC;
    float cnt  = fmaxf(g_cnt[t], 1.f);
    float2 a   = g_acc[idx];
    float mean = a.x / cnt;
    float var  = fmaxf(a.y / cnt - mean * mean, 0.f);
    g_mean[idx] = mean;
    g_rstd[idx] = 1.f / sqrtf(var + 1e-5f);
}

// ---------------------------------------------------------------------------
// Kernel 3: normalize.  Warp-per-row, float4 loads/stores, stats staged in
// shared as SEPARATE mean/rstd tables (conflict-free LDS.128 at stride 16B).
//   blockDim = 256 (8 warps); dyn smem: 2 * TC floats = 64KB.
// ---------------------------------------------------------------------------
#define NRM_U 4
__global__ void __launch_bounds__(256) k_norm(
    const float* __restrict__ x, const void* __restrict__ tv,
    float* __restrict__ out, long long N)
{
    extern __shared__ float sm[];
    float* smean = sm;        // TC
    float* srstd = sm + TC;   // TC
    const int tid = threadIdx.x;

    #pragma unroll
    for (int i = tid; i < TC; i += 256) {
        smean[i] = g_mean[i];
        srstd[i] = g_rstd[i];
    }
    __syncthreads();

    const int is64 = g_is64;
    const long long* __restrict__ tv64 = (const long long*)tv;
    const int*       __restrict__ tv32 = (const int*)tv;

    const int lane = tid & 31;
    const long long w  = (long long)blockIdx.x * 8 + (tid >> 5);
    const long long nw = (long long)gridDim.x * 8;
    const float4* __restrict__ x4 = (const float4*)x;
    float4* __restrict__ o4 = (float4*)out;

    for (long long r0 = w * NRM_U; r0 < N; r0 += nw * NRM_U) {
        float4 xv[NRM_U];
        int    ty[NRM_U];
        const int m = (N - r0 >= NRM_U) ? NRM_U : (int)(N - r0);

        #pragma unroll
        for (int u = 0; u < NRM_U; u++) {
            if (u < m) {
                long long r = r0 + u;
                ty[u] = is64 ? (int)tv64[r] : tv32[r];
                xv[u] = x4[r * (CC / 4) + lane];
            }
        }
        #pragma unroll
        for (int u = 0; u < NRM_U; u++) {
            if (u < m) {
                int o = ty[u] * CC + 4 * lane;
                float4 mn = *(const float4*)&smean[o];
                float4 rs = *(const float4*)&srstd[o];
                float4 res;
                res.x = (xv[u].x - mn.x) * rs.x;
                res.y = (xv[u].y - mn.y) * rs.y;
                res.z = (xv[u].z - mn.z) * rs.z;
                res.w = (xv[u].w - mn.w) * rs.w;
                o4[(r0 + u) * (CC / 4) + lane] = res;
            }
        }
    }
}

// ---------------------------------------------------------------------------
// Launch
// ---------------------------------------------------------------------------
extern "C" void kernel_launch(void* const* d_in, const int* in_sizes, int n_in,
                              void* d_out, int out_size)
{
    const float* x  = (const float*)d_in[0];
    const void*  tv = d_in[1];
    float* out = (float*)d_out;
    const long long N = (long long)in_sizes[1];   // rows (type_vec length)

    const int ACC_SMEM = TC * (int)sizeof(float2) + TT * (int)sizeof(float); // 65792
    const int NRM_SMEM = 2 * TC * (int)sizeof(float);                        // 65536

    cudaFuncSetAttribute(k_acc,  cudaFuncAttributeMaxDynamicSharedMemorySize, ACC_SMEM);
    cudaFuncSetAttribute(k_norm, cudaFuncAttributeMaxDynamicSharedMemorySize, NRM_SMEM);

    k_init<<<(TC + 255) / 256, 256>>>(tv, N);
    k_acc <<<444, 128, ACC_SMEM>>>(x, tv, N);     // 148 SMs * 3 blocks
    k_fin <<<(TC + 255) / 256, 256>>>();
    k_norm<<<444, 256, NRM_SMEM>>>(x, tv, out, N);
}